// round 9
// baseline (speedup 1.0000x reference)
#include <cuda_runtime.h>

#define N_NODES 200000
#define C_DIM 256
#define H_DIM 64
#define K_DIM 3
#define G_DIM 512

// ---------------- scratch (device globals; no allocation allowed) ----------
__device__ float    g_scores[N_NODES * K_DIM];
__device__ unsigned g_menc[G_DIM * K_DIM];
__device__ float    g_denom[G_DIM * K_DIM];
__device__ int      g_argmin[G_DIM * K_DIM];

// ---------------- helpers --------------------------------------------------
__device__ __forceinline__ unsigned fenc(float f) {
    unsigned u = __float_as_uint(f);
    return u ^ ((u >> 31) ? 0xFFFFFFFFu : 0x80000000u);
}
__device__ __forceinline__ float fdec(unsigned e) {
    unsigned u = (e & 0x80000000u) ? (e ^ 0x80000000u) : ~e;
    return __uint_as_float(u);
}
__device__ __forceinline__ float lrelu(float v) { return v > 0.f ? v : 0.01f * v; }
__device__ __forceinline__ int clampg(int g) { return min(max(g, 0), G_DIM - 1); }

__device__ __forceinline__ void fma2(unsigned long long& acc,
                                     unsigned long long a, unsigned long long b) {
    asm("fma.rn.f32x2 %0, %1, %2, %0;" : "+l"(acc) : "l"(a), "l"(b));
}
__device__ __forceinline__ unsigned long long dup2(float v) {
    unsigned long long r;
    unsigned u = __float_as_uint(v);
    asm("mov.b64 %0, {%1, %1};" : "=l"(r) : "r"(u));
    return r;
}
__device__ __forceinline__ void unpk2(unsigned long long v, float& lo, float& hi) {
    unsigned a, b;
    asm("mov.b64 {%0, %1}, %2;" : "=r"(a), "=r"(b) : "l"(v));
    lo = __uint_as_float(a); hi = __uint_as_float(b);
}

// ---------------- K0: init reduction buffers -------------------------------
__global__ void k_init() {
    int i = blockIdx.x * blockDim.x + threadIdx.x;
    if (i < G_DIM * K_DIM) {
        g_menc[i]   = 0u;
        g_denom[i]  = 0.f;
        g_argmin[i] = N_NODES;
    }
}

// ---------------- K1: scores (8x8 tile, FFMA2, pre-dup'd W1) ---------------
#define SC_ROWS 256      // rows per block (8 warps)
#define SC_CHUNK 16      // k-depth per stage
#define XS_PAD 260       // float stride (>=256 rows, 16B-aligned)
#define W1D_PAD 66       // u64 stride

__global__ __launch_bounds__(SC_ROWS) void k_scores(
    const float* __restrict__ x, const int* __restrict__ batch,
    const float* __restrict__ W1, const float* __restrict__ b1,
    const float* __restrict__ W2, const float* __restrict__ b2)
{
    __shared__ __align__(16) unsigned long long W1d[SC_CHUNK][W1D_PAD]; // 8.25 KB
    __shared__ __align__(16) float xs[SC_CHUNK][XS_PAD];                // 16.6 KB
    __shared__ float W2s[H_DIM * K_DIM];
    __shared__ float b1s[H_DIM];
    __shared__ float b2s[K_DIM];

    const int t  = threadIdx.x;
    const int r0 = blockIdx.x * SC_ROWS;
    const int rows = min(SC_ROWS, N_NODES - r0);
    const int rb = (t >> 3) * 8;    // 8-row group
    const int lh = t & 7;           // h lane: handles h = lh + 8q

    for (int i = t; i < H_DIM * K_DIM; i += SC_ROWS) W2s[i] = W2[i];
    if (t < H_DIM) b1s[t] = b1[t];
    if (t < K_DIM) b2s[t] = b2[t];

    unsigned long long acc[4][8];
#pragma unroll
    for (int p = 0; p < 4; p++)
#pragma unroll
        for (int q = 0; q < 8; q++) acc[p][q] = 0ull;

    for (int c0 = 0; c0 < C_DIM; c0 += SC_CHUNK) {
        __syncthreads();
        // stage W1 chunk duplicated: W1d[k][h] = {w,w}
        for (int i = t; i < SC_CHUNK * H_DIM; i += SC_ROWS) {
            int k = i >> 6, h = i & 63;
            W1d[k][h] = dup2(W1[(size_t)(c0 + k) * H_DIM + h]);
        }
        // stage x tile [256 rows][16 k] -> xs[k][row]
        for (int f = t; f < SC_ROWS * (SC_CHUNK / 4); f += SC_ROWS) {
            int row = f >> 2, c4 = f & 3;
            if (row < rows) {
                float4 v = *(const float4*)(x + (size_t)(r0 + row) * C_DIM + c0 + 4 * c4);
                xs[4 * c4 + 0][row] = v.x;
                xs[4 * c4 + 1][row] = v.y;
                xs[4 * c4 + 2][row] = v.z;
                xs[4 * c4 + 3][row] = v.w;
            }
        }
        __syncthreads();
#pragma unroll 2
        for (int j = 0; j < SC_CHUNK; j++) {
            ulonglong2 xa = *(const ulonglong2*)&xs[j][rb];
            ulonglong2 xb = *(const ulonglong2*)&xs[j][rb + 4];
            unsigned long long xr[4] = {xa.x, xa.y, xb.x, xb.y};
            unsigned long long w[8];
#pragma unroll
            for (int q = 0; q < 8; q++) w[q] = W1d[j][lh + 8 * q];
#pragma unroll
            for (int p = 0; p < 4; p++)
#pragma unroll
                for (int q = 0; q < 8; q++)
                    fma2(acc[p][q], xr[p], w[q]);
        }
    }

    // epilogue: bias + lrelu + @W2 partials, 8-lane butterfly reduce
    float scp[8][K_DIM];
#pragma unroll
    for (int i = 0; i < 8; i++)
#pragma unroll
        for (int k = 0; k < K_DIM; k++) scp[i][k] = 0.f;

#pragma unroll
    for (int p = 0; p < 4; p++)
#pragma unroll
        for (int q = 0; q < 8; q++) {
            float lo, hi; unpk2(acc[p][q], lo, hi);
            int h = lh + 8 * q;
            float hv0 = lrelu(lo + b1s[h]);
            float hv1 = lrelu(hi + b1s[h]);
#pragma unroll
            for (int k = 0; k < K_DIM; k++) {
                float w = W2s[h * K_DIM + k];
                scp[2 * p + 0][k] = fmaf(hv0, w, scp[2 * p + 0][k]);
                scp[2 * p + 1][k] = fmaf(hv1, w, scp[2 * p + 1][k]);
            }
        }

    const unsigned FULL = 0xFFFFFFFFu;
#pragma unroll
    for (int o = 1; o < 8; o <<= 1)
#pragma unroll
        for (int i = 0; i < 8; i++)
#pragma unroll
            for (int k = 0; k < K_DIM; k++)
                scp[i][k] += __shfl_xor_sync(FULL, scp[i][k], o);

    int lr = t & 7;
    int n = r0 + rb + lr;
    if (n < N_NODES) {
        int g = clampg(batch[n]);
#pragma unroll
        for (int k = 0; k < K_DIM; k++) {
            float s = scp[lr][k] + b2s[k];
            g_scores[(size_t)n * K_DIM + k] = s;
            atomicMax(&g_menc[g * K_DIM + k], fenc(s));
        }
    }
}

// ---------------- K2: exp-sum (denom) + argmin of argmax -------------------
__global__ void k_reduce(const int* __restrict__ batch) {
    int n = blockIdx.x * blockDim.x + threadIdx.x;
    if (n >= N_NODES) return;
    int g = clampg(batch[n]);
#pragma unroll
    for (int k = 0; k < K_DIM; k++) {
        float s = g_scores[(size_t)n * K_DIM + k];
        float m = fdec(g_menc[g * K_DIM + k]);
        float e = expf(s - m);
        atomicAdd(&g_denom[g * K_DIM + k], e);
        if (s == m) atomicMin(&g_argmin[g * K_DIM + k], n);
    }
}

// ---------------- K3: gather + feat@Wh + lrelu (128 blocks, r-split 4) -----
#define GPB 4
#define KF_THREADS 1024
__global__ __launch_bounds__(KF_THREADS) void k_final(
    const float* __restrict__ x, const int* __restrict__ batch,
    const float* __restrict__ Wh, const float* __restrict__ bh,
    float* __restrict__ out)
{
    __shared__ float feat[GPB][K_DIM * C_DIM];   // 12 KB; reused as reduce buf
    __shared__ float sg_s[GPB][K_DIM];
    __shared__ int   idx_s[GPB][K_DIM];

    const int t  = threadIdx.x;
    const int g0 = blockIdx.x * GPB;

    if (t < GPB * K_DIM) {
        int gi = t / K_DIM, k = t % K_DIM;
        int g = g0 + gi;
        int idx = min(g_argmin[g * K_DIM + k], N_NODES - 1);
        int gb = clampg(batch[idx]);
        float m = fdec(g_menc[gb * K_DIM + k]);
        float sg = expf(g_scores[(size_t)idx * K_DIM + k] - m) / g_denom[gb * K_DIM + k];
        sg_s[gi][k] = sg;
        idx_s[gi][k] = idx;
    }
    __syncthreads();

    for (int idx = t; idx < GPB * K_DIM * C_DIM; idx += KF_THREADS) {
        int gi = idx / (K_DIM * C_DIM);
        int rem = idx - gi * (K_DIM * C_DIM);
        int k = rem >> 8, c = rem & 255;
        feat[gi][rem] = x[(size_t)idx_s[gi][k] * C_DIM + c] * sg_s[gi][k];
    }
    __syncthreads();

    const int col = t & 255;
    const int rs  = t >> 8;         // 0..3, 192 r each
    float acc[GPB];
#pragma unroll
    for (int gi = 0; gi < GPB; gi++) acc[gi] = 0.f;

    const int rbeg = rs * 192;
#pragma unroll 4
    for (int r = rbeg; r < rbeg + 192; r++) {
        float wv = __ldg(&Wh[(size_t)r * C_DIM + col]);
#pragma unroll
        for (int gi = 0; gi < GPB; gi++) acc[gi] = fmaf(feat[gi][r], wv, acc[gi]);
    }

    __syncthreads();   // feat reads done; reuse as reduce buffer (3072 floats)
    float* red = &feat[0][0];
    if (rs > 0) {
#pragma unroll
        for (int gi = 0; gi < GPB; gi++)
            red[((rs - 1) * GPB + gi) * C_DIM + col] = acc[gi];
    }
    __syncthreads();
    if (rs == 0) {
        float bhv = __ldg(&bh[col]);
#pragma unroll
        for (int gi = 0; gi < GPB; gi++) {
            float v = acc[gi]
                    + red[(0 * GPB + gi) * C_DIM + col]
                    + red[(1 * GPB + gi) * C_DIM + col]
                    + red[(2 * GPB + gi) * C_DIM + col]
                    + bhv;
            out[(size_t)(g0 + gi) * C_DIM + col] = lrelu(v);
        }
    }
}

// ---------------- launch: bind inputs by UNIQUE element count ---------------
extern "C" void kernel_launch(void* const* d_in, const int* in_sizes, int n_in,
                              void* d_out, int out_size) {
    const int want[8] = {51200000, 200000, 16384, 64, 192, 3, 196608, 256};
    const void* p[8];
    for (int r = 0; r < 8; r++) p[r] = (r < n_in) ? d_in[r] : nullptr;
    for (int r = 0; r < 8; r++)
        for (int i = 0; i < n_in; i++)
            if (in_sizes[i] == want[r]) { p[r] = d_in[i]; break; }

    const float* x     = (const float*)p[0];
    const int*   batch = (const int*)p[1];
    const float* W1    = (const float*)p[2];
    const float* b1    = (const float*)p[3];
    const float* W2    = (const float*)p[4];
    const float* b2    = (const float*)p[5];
    const float* Wh    = (const float*)p[6];
    const float* bh    = (const float*)p[7];
    float* out = (float*)d_out;

    k_init<<<(G_DIM * K_DIM + 255) / 256, 256>>>();
    k_scores<<<(N_NODES + SC_ROWS - 1) / SC_ROWS, SC_ROWS>>>(x, batch, W1, b1, W2, b2);
    k_reduce<<<(N_NODES + 255) / 256, 256>>>(batch);
    k_final<<<G_DIM / GPB, KF_THREADS>>>(x, batch, Wh, bh, out);
}

// round 10
// speedup vs baseline: 1.0500x; 1.0500x over previous
#include <cuda_runtime.h>

#define N_NODES 200000
#define C_DIM 256
#define H_DIM 64
#define K_DIM 3
#define G_DIM 512

// ---------------- scratch (device globals; no allocation allowed) ----------
__device__ float    g_scores[N_NODES * K_DIM];
__device__ unsigned g_menc[G_DIM * K_DIM];
__device__ float    g_denom[G_DIM * K_DIM];
__device__ int      g_argmin[G_DIM * K_DIM];

// ---------------- helpers --------------------------------------------------
__device__ __forceinline__ unsigned fenc(float f) {
    unsigned u = __float_as_uint(f);
    return u ^ ((u >> 31) ? 0xFFFFFFFFu : 0x80000000u);
}
__device__ __forceinline__ float fdec(unsigned e) {
    unsigned u = (e & 0x80000000u) ? (e ^ 0x80000000u) : ~e;
    return __uint_as_float(u);
}
__device__ __forceinline__ float lrelu(float v) { return v > 0.f ? v : 0.01f * v; }
__device__ __forceinline__ int clampg(int g) { return min(max(g, 0), G_DIM - 1); }

__device__ __forceinline__ void fma2(unsigned long long& acc,
                                     unsigned long long a, unsigned long long b) {
    asm("fma.rn.f32x2 %0, %1, %2, %0;" : "+l"(acc) : "l"(a), "l"(b));
}
__device__ __forceinline__ unsigned long long dup2(float v) {
    unsigned long long r;
    unsigned u = __float_as_uint(v);
    asm("mov.b64 %0, {%1, %1};" : "=l"(r) : "r"(u));
    return r;
}
__device__ __forceinline__ void unpk2(unsigned long long v, float& lo, float& hi) {
    unsigned a, b;
    asm("mov.b64 {%0, %1}, %2;" : "=r"(a), "=r"(b) : "l"(v));
    lo = __uint_as_float(a); hi = __uint_as_float(b);
}

// ---------------- K0: init reduction buffers -------------------------------
__global__ void k_init() {
    int i = blockIdx.x * blockDim.x + threadIdx.x;
    if (i < G_DIM * K_DIM) {
        g_menc[i]   = 0u;
        g_denom[i]  = 0.f;
        g_argmin[i] = N_NODES;
    }
}

// ---------------- K1: scores (4x8 tile, FFMA2, pre-dup'd W1) ---------------
#define SC_THREADS 128
#define SC_ROWS 64       // rows per block -> 3125 blocks, no tail
#define SC_CHUNK 32      // k-depth per stage
#define XS_PAD 68        // float stride (64 rows + pad, 16B aligned)
#define W1D_PAD 66       // u64 stride

__global__ __launch_bounds__(SC_THREADS) void k_scores(
    const float* __restrict__ x, const int* __restrict__ batch,
    const float* __restrict__ W1, const float* __restrict__ b1,
    const float* __restrict__ W2, const float* __restrict__ b2)
{
    __shared__ __align__(16) unsigned long long W1d[SC_CHUNK][W1D_PAD]; // 16.5 KB
    __shared__ __align__(16) float xs[SC_CHUNK][XS_PAD];                // 8.5 KB
    __shared__ float W2s[H_DIM * K_DIM];
    __shared__ float b1s[H_DIM];
    __shared__ float b2s[K_DIM];

    const int t  = threadIdx.x;
    const int r0 = blockIdx.x * SC_ROWS;
    const int lh = t & 7;           // h lane: handles h = lh + 8q
    const int rb = (t >> 3) * 4;    // 4-row group (16 groups x 4 = 64 rows)

    for (int i = t; i < H_DIM * K_DIM; i += SC_THREADS) W2s[i] = W2[i];
    if (t < H_DIM) b1s[t] = b1[t];
    if (t < K_DIM) b2s[t] = b2[t];

    unsigned long long acc[2][8];   // 2 row-pairs x 8 h
#pragma unroll
    for (int p = 0; p < 2; p++)
#pragma unroll
        for (int q = 0; q < 8; q++) acc[p][q] = 0ull;

    for (int c0 = 0; c0 < C_DIM; c0 += SC_CHUNK) {
        __syncthreads();
        // stage W1 chunk pre-duplicated: W1d[k][h] = {w,w}  (2048 elems, 16/thread)
        for (int i = t; i < SC_CHUNK * H_DIM; i += SC_THREADS) {
            int k = i >> 6, h = i & 63;
            W1d[k][h] = dup2(W1[(size_t)(c0 + k) * H_DIM + h]);
        }
        // stage x tile [64 rows][32 k] -> xs[k][row]  (512 float4, 4/thread)
        for (int f = t; f < SC_ROWS * (SC_CHUNK / 4); f += SC_THREADS) {
            int row = f >> 3, c4 = f & 7;
            float4 v = *(const float4*)(x + (size_t)(r0 + row) * C_DIM + c0 + 4 * c4);
            xs[4 * c4 + 0][row] = v.x;
            xs[4 * c4 + 1][row] = v.y;
            xs[4 * c4 + 2][row] = v.z;
            xs[4 * c4 + 3][row] = v.w;
        }
        __syncthreads();
#pragma unroll 4
        for (int j = 0; j < SC_CHUNK; j++) {
            // 4 rows = 2 packed f32x2 pairs via one LDS.128 (broadcast across 8 lanes)
            ulonglong2 xa = *(const ulonglong2*)&xs[j][rb];
            unsigned long long xr[2] = {xa.x, xa.y};
            unsigned long long w[8];
#pragma unroll
            for (int q = 0; q < 8; q++) w[q] = W1d[j][lh + 8 * q];
#pragma unroll
            for (int p = 0; p < 2; p++)
#pragma unroll
                for (int q = 0; q < 8; q++)
                    fma2(acc[p][q], xr[p], w[q]);
        }
    }

    // epilogue: bias + lrelu + @W2 partials for 4 local rows, butterfly over 8 lanes
    float scp[4][K_DIM];
#pragma unroll
    for (int i = 0; i < 4; i++)
#pragma unroll
        for (int k = 0; k < K_DIM; k++) scp[i][k] = 0.f;

#pragma unroll
    for (int p = 0; p < 2; p++)
#pragma unroll
        for (int q = 0; q < 8; q++) {
            float lo, hi; unpk2(acc[p][q], lo, hi);
            int h = lh + 8 * q;
            float hv0 = lrelu(lo + b1s[h]);
            float hv1 = lrelu(hi + b1s[h]);
#pragma unroll
            for (int k = 0; k < K_DIM; k++) {
                float w = W2s[h * K_DIM + k];
                scp[2 * p + 0][k] = fmaf(hv0, w, scp[2 * p + 0][k]);
                scp[2 * p + 1][k] = fmaf(hv1, w, scp[2 * p + 1][k]);
            }
        }

    const unsigned FULL = 0xFFFFFFFFu;
#pragma unroll
    for (int o = 1; o < 8; o <<= 1)
#pragma unroll
        for (int i = 0; i < 4; i++)
#pragma unroll
            for (int k = 0; k < K_DIM; k++)
                scp[i][k] += __shfl_xor_sync(FULL, scp[i][k], o);

    // lanes 0..3 of each 8-lane group write rows 0..3
    if (lh < 4) {
        int n = r0 + rb + lh;      // always < N_NODES (3125*64 == 200000)
        int g = clampg(batch[n]);
#pragma unroll
        for (int k = 0; k < K_DIM; k++) {
            float s = scp[lh][k] + b2s[k];
            g_scores[(size_t)n * K_DIM + k] = s;
            atomicMax(&g_menc[g * K_DIM + k], fenc(s));
        }
    }
}

// ---------------- K2: exp-sum (denom) + argmin of argmax -------------------
__global__ void k_reduce(const int* __restrict__ batch) {
    int n = blockIdx.x * blockDim.x + threadIdx.x;
    if (n >= N_NODES) return;
    int g = clampg(batch[n]);
#pragma unroll
    for (int k = 0; k < K_DIM; k++) {
        float s = g_scores[(size_t)n * K_DIM + k];
        float m = fdec(g_menc[g * K_DIM + k]);
        float e = expf(s - m);
        atomicAdd(&g_denom[g * K_DIM + k], e);
        if (s == m) atomicMin(&g_argmin[g * K_DIM + k], n);
    }
}

// ---------------- K3: gather + feat@Wh + lrelu (128 blocks, r-split 4) -----
#define GPB 4
#define KF_THREADS 1024
__global__ __launch_bounds__(KF_THREADS) void k_final(
    const float* __restrict__ x, const int* __restrict__ batch,
    const float* __restrict__ Wh, const float* __restrict__ bh,
    float* __restrict__ out)
{
    __shared__ float feat[GPB][K_DIM * C_DIM];   // 12 KB; reused as reduce buf
    __shared__ float sg_s[GPB][K_DIM];
    __shared__ int   idx_s[GPB][K_DIM];

    const int t  = threadIdx.x;
    const int g0 = blockIdx.x * GPB;

    if (t < GPB * K_DIM) {
        int gi = t / K_DIM, k = t % K_DIM;
        int g = g0 + gi;
        int idx = min(g_argmin[g * K_DIM + k], N_NODES - 1);
        int gb = clampg(batch[idx]);
        float m = fdec(g_menc[gb * K_DIM + k]);
        float sg = expf(g_scores[(size_t)idx * K_DIM + k] - m) / g_denom[gb * K_DIM + k];
        sg_s[gi][k] = sg;
        idx_s[gi][k] = idx;
    }
    __syncthreads();

    for (int idx = t; idx < GPB * K_DIM * C_DIM; idx += KF_THREADS) {
        int gi = idx / (K_DIM * C_DIM);
        int rem = idx - gi * (K_DIM * C_DIM);
        int k = rem >> 8, c = rem & 255;
        feat[gi][rem] = x[(size_t)idx_s[gi][k] * C_DIM + c] * sg_s[gi][k];
    }
    __syncthreads();

    const int col = t & 255;
    const int rs  = t >> 8;         // 0..3, 192 r each
    float acc[GPB];
#pragma unroll
    for (int gi = 0; gi < GPB; gi++) acc[gi] = 0.f;

    const int rbeg = rs * 192;
#pragma unroll 8
    for (int r = rbeg; r < rbeg + 192; r++) {
        float wv = __ldg(&Wh[(size_t)r * C_DIM + col]);
#pragma unroll
        for (int gi = 0; gi < GPB; gi++) acc[gi] = fmaf(feat[gi][r], wv, acc[gi]);
    }

    __syncthreads();
    float* red = &feat[0][0];
    if (rs > 0) {
#pragma unroll
        for (int gi = 0; gi < GPB; gi++)
            red[((rs - 1) * GPB + gi) * C_DIM + col] = acc[gi];
    }
    __syncthreads();
    if (rs == 0) {
        float bhv = __ldg(&bh[col]);
#pragma unroll
        for (int gi = 0; gi < GPB; gi++) {
            float v = acc[gi]
                    + red[(0 * GPB + gi) * C_DIM + col]
                    + red[(1 * GPB + gi) * C_DIM + col]
                    + red[(2 * GPB + gi) * C_DIM + col]
                    + bhv;
            out[(size_t)(g0 + gi) * C_DIM + col] = lrelu(v);
        }
    }
}

// ---------------- launch: bind inputs by UNIQUE element count ---------------
extern "C" void kernel_launch(void* const* d_in, const int* in_sizes, int n_in,
                              void* d_out, int out_size) {
    const int want[8] = {51200000, 200000, 16384, 64, 192, 3, 196608, 256};
    const void* p[8];
    for (int r = 0; r < 8; r++) p[r] = (r < n_in) ? d_in[r] : nullptr;
    for (int r = 0; r < 8; r++)
        for (int i = 0; i < n_in; i++)
            if (in_sizes[i] == want[r]) { p[r] = d_in[i]; break; }

    const float* x     = (const float*)p[0];
    const int*   batch = (const int*)p[1];
    const float* W1    = (const float*)p[2];
    const float* b1    = (const float*)p[3];
    const float* W2    = (const float*)p[4];
    const float* b2    = (const float*)p[5];
    const float* Wh    = (const float*)p[6];
    const float* bh    = (const float*)p[7];
    float* out = (float*)d_out;

    k_init<<<(G_DIM * K_DIM + 255) / 256, 256>>>();
    k_scores<<<N_NODES / SC_ROWS, SC_THREADS>>>(x, batch, W1, b1, W2, b2);
    k_reduce<<<(N_NODES + 255) / 256, 256>>>(batch);
    k_final<<<G_DIM / GPB, KF_THREADS>>>(x, batch, Wh, bh, out);
}

// round 11
// speedup vs baseline: 1.2129x; 1.1552x over previous
#include <cuda_runtime.h>

#define N_NODES 200000
#define C_DIM 256
#define H_DIM 64
#define K_DIM 3
#define G_DIM 512

// ---------------- scratch (device globals; no allocation allowed) ----------
__device__ float    g_scores[N_NODES * K_DIM];
__device__ unsigned g_menc[G_DIM * K_DIM];
__device__ float    g_denom[G_DIM * K_DIM];
__device__ int      g_argmin[G_DIM * K_DIM];

// ---------------- helpers --------------------------------------------------
__device__ __forceinline__ unsigned fenc(float f) {
    unsigned u = __float_as_uint(f);
    return u ^ ((u >> 31) ? 0xFFFFFFFFu : 0x80000000u);
}
__device__ __forceinline__ float fdec(unsigned e) {
    unsigned u = (e & 0x80000000u) ? (e ^ 0x80000000u) : ~e;
    return __uint_as_float(u);
}
__device__ __forceinline__ float lrelu(float v) { return v > 0.f ? v : 0.01f * v; }
__device__ __forceinline__ int clampg(int g) { return min(max(g, 0), G_DIM - 1); }

__device__ __forceinline__ void fma2(unsigned long long& acc,
                                     unsigned long long a, unsigned long long b) {
    asm("fma.rn.f32x2 %0, %1, %2, %0;" : "+l"(acc) : "l"(a), "l"(b));
}
__device__ __forceinline__ unsigned long long dup2(float v) {
    unsigned long long r;
    unsigned u = __float_as_uint(v);
    asm("mov.b64 %0, {%1, %1};" : "=l"(r) : "r"(u));
    return r;
}
__device__ __forceinline__ void unpk2(unsigned long long v, float& lo, float& hi) {
    unsigned a, b;
    asm("mov.b64 {%0, %1}, %2;" : "=r"(a), "=r"(b) : "l"(v));
    lo = __uint_as_float(a); hi = __uint_as_float(b);
}

// ---------------- K0: init reduction buffers -------------------------------
__global__ void k_init() {
    int i = blockIdx.x * blockDim.x + threadIdx.x;
    if (i < G_DIM * K_DIM) {
        g_menc[i]   = 0u;
        g_denom[i]  = 0.f;
        g_argmin[i] = N_NODES;
    }
}

// ---------------- K1: scores (8x8 tile, FFMA2, pre-dup'd W1, 128 rows) -----
#define SC_THREADS 128
#define SC_ROWS 128      // rows per block
#define SC_CHUNK 32      // k-depth per stage
#define XS_PAD 132       // float stride (128 rows + pad, 16B aligned)
#define W1D_PAD 66       // u64 stride

__global__ __launch_bounds__(SC_THREADS) void k_scores(
    const float* __restrict__ x, const int* __restrict__ batch,
    const float* __restrict__ W1, const float* __restrict__ b1,
    const float* __restrict__ W2, const float* __restrict__ b2)
{
    __shared__ __align__(16) unsigned long long W1d[SC_CHUNK][W1D_PAD]; // 16.5 KB
    __shared__ __align__(16) float xs[SC_CHUNK][XS_PAD];                // 16.5 KB
    __shared__ float W2s[H_DIM * K_DIM];
    __shared__ float b1s[H_DIM];
    __shared__ float b2s[K_DIM];

    const int t  = threadIdx.x;
    const int r0 = blockIdx.x * SC_ROWS;
    const int rows = min(SC_ROWS, N_NODES - r0);
    const int rb = (t >> 3) * 8;    // 8-row group (16 groups)
    const int lh = t & 7;           // h lane: handles h = lh + 8q

    for (int i = t; i < H_DIM * K_DIM; i += SC_THREADS) W2s[i] = W2[i];
    if (t < H_DIM) b1s[t] = b1[t];
    if (t < K_DIM) b2s[t] = b2[t];

    unsigned long long acc[4][8];   // 4 row-pairs x 8 h
#pragma unroll
    for (int p = 0; p < 4; p++)
#pragma unroll
        for (int q = 0; q < 8; q++) acc[p][q] = 0ull;

    for (int c0 = 0; c0 < C_DIM; c0 += SC_CHUNK) {
        __syncthreads();
        // stage W1 chunk pre-duplicated: W1d[k][h] = {w,w}
        for (int i = t; i < SC_CHUNK * H_DIM; i += SC_THREADS) {
            int k = i >> 6, h = i & 63;
            W1d[k][h] = dup2(W1[(size_t)(c0 + k) * H_DIM + h]);
        }
        // stage x tile [128 rows][32 k] -> xs[k][row]
        for (int f = t; f < SC_ROWS * (SC_CHUNK / 4); f += SC_THREADS) {
            int row = f >> 3, c4 = f & 7;
            if (row < rows) {
                float4 v = *(const float4*)(x + (size_t)(r0 + row) * C_DIM + c0 + 4 * c4);
                xs[4 * c4 + 0][row] = v.x;
                xs[4 * c4 + 1][row] = v.y;
                xs[4 * c4 + 2][row] = v.z;
                xs[4 * c4 + 3][row] = v.w;
            }
        }
        __syncthreads();
#pragma unroll 2
        for (int j = 0; j < SC_CHUNK; j++) {
            ulonglong2 xa = *(const ulonglong2*)&xs[j][rb];
            ulonglong2 xb = *(const ulonglong2*)&xs[j][rb + 4];
            unsigned long long xr[4] = {xa.x, xa.y, xb.x, xb.y};
            unsigned long long w[8];
#pragma unroll
            for (int q = 0; q < 8; q++) w[q] = W1d[j][lh + 8 * q];
#pragma unroll
            for (int p = 0; p < 4; p++)
#pragma unroll
                for (int q = 0; q < 8; q++)
                    fma2(acc[p][q], xr[p], w[q]);
        }
    }

    // epilogue: bias + lrelu + @W2 partials for 8 local rows, butterfly over 8 lanes
    float scp[8][K_DIM];
#pragma unroll
    for (int i = 0; i < 8; i++)
#pragma unroll
        for (int k = 0; k < K_DIM; k++) scp[i][k] = 0.f;

#pragma unroll
    for (int p = 0; p < 4; p++)
#pragma unroll
        for (int q = 0; q < 8; q++) {
            float lo, hi; unpk2(acc[p][q], lo, hi);
            int h = lh + 8 * q;
            float hv0 = lrelu(lo + b1s[h]);
            float hv1 = lrelu(hi + b1s[h]);
#pragma unroll
            for (int k = 0; k < K_DIM; k++) {
                float w = W2s[h * K_DIM + k];
                scp[2 * p + 0][k] = fmaf(hv0, w, scp[2 * p + 0][k]);
                scp[2 * p + 1][k] = fmaf(hv1, w, scp[2 * p + 1][k]);
            }
        }

    const unsigned FULL = 0xFFFFFFFFu;
#pragma unroll
    for (int o = 1; o < 8; o <<= 1)
#pragma unroll
        for (int i = 0; i < 8; i++)
#pragma unroll
            for (int k = 0; k < K_DIM; k++)
                scp[i][k] += __shfl_xor_sync(FULL, scp[i][k], o);

    // lane (t&7) takes row rb + (t&7)
    int lr = t & 7;
    int n = r0 + rb + lr;
    if (n < N_NODES) {
        int g = clampg(batch[n]);
#pragma unroll
        for (int k = 0; k < K_DIM; k++) {
            float s = scp[lr][k] + b2s[k];
            g_scores[(size_t)n * K_DIM + k] = s;
            atomicMax(&g_menc[g * K_DIM + k], fenc(s));
        }
    }
}

// ---------------- K2: exp-sum (denom) + argmin of argmax -------------------
__global__ void k_reduce(const int* __restrict__ batch) {
    int n = blockIdx.x * blockDim.x + threadIdx.x;
    if (n >= N_NODES) return;
    int g = clampg(batch[n]);
#pragma unroll
    for (int k = 0; k < K_DIM; k++) {
        float s = g_scores[(size_t)n * K_DIM + k];
        float m = fdec(g_menc[g * K_DIM + k]);
        float e = expf(s - m);
        atomicAdd(&g_denom[g * K_DIM + k], e);
        if (s == m) atomicMin(&g_argmin[g * K_DIM + k], n);
    }
}

// ---------------- K3: gather + feat@Wh + lrelu (128 blocks, r-split 4) -----
#define GPB 4
#define KF_THREADS 1024
__global__ __launch_bounds__(KF_THREADS) void k_final(
    const float* __restrict__ x, const int* __restrict__ batch,
    const float* __restrict__ Wh, const float* __restrict__ bh,
    float* __restrict__ out)
{
    __shared__ float feat[GPB][K_DIM * C_DIM];   // 12 KB; reused as reduce buf
    __shared__ float sg_s[GPB][K_DIM];
    __shared__ int   idx_s[GPB][K_DIM];

    const int t  = threadIdx.x;
    const int g0 = blockIdx.x * GPB;

    if (t < GPB * K_DIM) {
        int gi = t / K_DIM, k = t % K_DIM;
        int g = g0 + gi;
        int idx = min(g_argmin[g * K_DIM + k], N_NODES - 1);
        int gb = clampg(batch[idx]);
        float m = fdec(g_menc[gb * K_DIM + k]);
        float sg = expf(g_scores[(size_t)idx * K_DIM + k] - m) / g_denom[gb * K_DIM + k];
        sg_s[gi][k] = sg;
        idx_s[gi][k] = idx;
    }
    __syncthreads();

    for (int idx = t; idx < GPB * K_DIM * C_DIM; idx += KF_THREADS) {
        int gi = idx / (K_DIM * C_DIM);
        int rem = idx - gi * (K_DIM * C_DIM);
        int k = rem >> 8, c = rem & 255;
        feat[gi][rem] = x[(size_t)idx_s[gi][k] * C_DIM + c] * sg_s[gi][k];
    }
    __syncthreads();

    const int col = t & 255;
    const int rs  = t >> 8;         // 0..3, 192 r each
    float acc[GPB];
#pragma unroll
    for (int gi = 0; gi < GPB; gi++) acc[gi] = 0.f;

    const int rbeg = rs * 192;
#pragma unroll 8
    for (int r = rbeg; r < rbeg + 192; r++) {
        float wv = __ldg(&Wh[(size_t)r * C_DIM + col]);
#pragma unroll
        for (int gi = 0; gi < GPB; gi++) acc[gi] = fmaf(feat[gi][r], wv, acc[gi]);
    }

    __syncthreads();
    float* red = &feat[0][0];
    if (rs > 0) {
#pragma unroll
        for (int gi = 0; gi < GPB; gi++)
            red[((rs - 1) * GPB + gi) * C_DIM + col] = acc[gi];
    }
    __syncthreads();
    if (rs == 0) {
        float bhv = __ldg(&bh[col]);
#pragma unroll
        for (int gi = 0; gi < GPB; gi++) {
            float v = acc[gi]
                    + red[(0 * GPB + gi) * C_DIM + col]
                    + red[(1 * GPB + gi) * C_DIM + col]
                    + red[(2 * GPB + gi) * C_DIM + col]
                    + bhv;
            out[(size_t)(g0 + gi) * C_DIM + col] = lrelu(v);
        }
    }
}

// ---------------- launch: bind inputs by UNIQUE element count ---------------
extern "C" void kernel_launch(void* const* d_in, const int* in_sizes, int n_in,
                              void* d_out, int out_size) {
    const int want[8] = {51200000, 200000, 16384, 64, 192, 3, 196608, 256};
    const void* p[8];
    for (int r = 0; r < 8; r++) p[r] = (r < n_in) ? d_in[r] : nullptr;
    for (int r = 0; r < 8; r++)
        for (int i = 0; i < n_in; i++)
            if (in_sizes[i] == want[r]) { p[r] = d_in[i]; break; }

    const float* x     = (const float*)p[0];
    const int*   batch = (const int*)p[1];
    const float* W1    = (const float*)p[2];
    const float* b1    = (const float*)p[3];
    const float* W2    = (const float*)p[4];
    const float* b2    = (const float*)p[5];
    const float* Wh    = (const float*)p[6];
    const float* bh    = (const float*)p[7];
    float* out = (float*)d_out;

    k_init<<<(G_DIM * K_DIM + 255) / 256, 256>>>();
    k_scores<<<(N_NODES + SC_ROWS - 1) / SC_ROWS, SC_THREADS>>>(x, batch, W1, b1, W2, b2);
    k_reduce<<<(N_NODES + 255) / 256, 256>>>(batch);
    k_final<<<G_DIM / GPB, KF_THREADS>>>(x, batch, Wh, bh, out);
}